// round 1
// baseline (speedup 1.0000x reference)
#include <cuda_runtime.h>
#include <cuda_bf16.h>

#define NRES 768
#define EPSF 1e-6f
#define INFF 1e8f

// Block = one (t, i) row. Phase 1: build per-j metadata in smem.
// Phase 2: 256 threads = 16 j-lanes x 16 o-groups (4 outputs each), gather-combine
// columns of W (in smem, transposed) and stream float4 stores.
__global__ __launch_bounds__(256) void tpe_kernel(
    const float* __restrict__ pos,      // [T,768,37,3]
    const float* __restrict__ tpb,      // [T,768,3]
    const float* __restrict__ pbmask,   // [T,768]
    const float* __restrict__ aamask,   // [T,768,37]
    const int*   __restrict__ aatype,   // [T,768]
    const float* __restrict__ W,        // [64,88] row-major
    const float* __restrict__ bvec,     // [64]
    float* __restrict__ out)            // [T,768,768,64]
{
    __shared__ float  Wsm[88 * 64];     // Wsm[c*64 + o] = W[o,c]
    __shared__ float4 jA[NRES];         // (uv.x, uv.y, uv.z, f2d)
    __shared__ float4 jB[NRES];         // (pb2d, bitcast kbin, bitcast aa_j, 0)

    const int bid = blockIdx.x;         // t*768 + i
    const int t   = bid / NRES;
    const int i   = bid - t * NRES;
    const int tid = threadIdx.x;

    // ---- load W transposed into smem ----
    for (int idx = tid; idx < 88 * 64; idx += 256) {
        int c = idx >> 6, o = idx & 63;
        Wsm[c * 64 + o] = W[o * 88 + c];
    }

    // ---- per-row-i frame (every thread computes; loads broadcast from L1) ----
    const int   rowi = t * NRES + i;
    const float* posi = pos + (long)rowi * 37 * 3;
    const float cax = posi[3], cay = posi[4], caz = posi[5];
    // N, C relative to CA
    const float n0 = posi[0] - cax, n1 = posi[1] - cay, n2 = posi[2] - caz;
    const float c0 = posi[6] - cax, c1v = posi[7] - cay, c2v = posi[8] - caz;

    const float hxy   = c0 * c0 + c1v * c1v;
    const float norm1 = sqrtf(EPSF + hxy);
    const float s1  = -c1v / norm1, co1 = c0 / norm1;
    const float norm2 = sqrtf(EPSF + hxy + c2v * c2v);
    const float s2  = c2v / norm2, co2 = sqrtf(hxy) / norm2;

    // c_rots = c2 @ c1
    // row0: [ co2*co1, -co2*s1,  s2 ]
    // row1: [ s1,       co1,     0  ]
    // row2: [ -s2*co1,  s2*s1,   co2]
    const float nr1 = s1 * n0 + co1 * n1;
    const float nr2 = -s2 * co1 * n0 + s2 * s1 * n1 + co2 * n2;
    const float norm3 = sqrtf(EPSF + nr1 * nr1 + nr2 * nr2);
    const float sn = -nr2 / norm3, cn = nr1 / norm3;

    // M = nr @ c_rots  (rigid_vec = M @ (ca_j - ca_i))
    const float M00 = co2 * co1;
    const float M01 = -co2 * s1;
    const float M02 = s2;
    const float M10 = cn * s1 + sn * s2 * co1;
    const float M11 = cn * co1 - sn * s2 * s1;
    const float M12 = -sn * co2;
    const float M20 = sn * s1 - cn * s2 * co1;
    const float M21 = sn * co1 + cn * s2 * s1;
    const float M22 = cn * co2;

    const float fmask_i = aamask[rowi * 37 + 0] * aamask[rowi * 37 + 1] * aamask[rowi * 37 + 2];
    const float pbm_i   = pbmask[rowi];
    const float pbix = tpb[rowi * 3 + 0], pbiy = tpb[rowi * 3 + 1], pbiz = tpb[rowi * 3 + 2];
    const int   aai  = aatype[rowi];

    // ---- phase 1: per-j metadata ----
    for (int j = tid; j < NRES; j += 256) {
        const int rowj = t * NRES + j;
        const float* pbj = tpb + rowj * 3;
        float dx = pbix - pbj[0], dy = pbiy - pbj[1], dz = pbiz - pbj[2];
        float d2 = dx * dx + dy * dy + dz * dz;

        int cnt = 0;
#pragma unroll
        for (int k = 0; k < 39; k++) {
            float bk = 3.25f + 1.25f * (float)k;   // exact fp32 (multiples of 0.25)
            cnt += (d2 > bk * bk) ? 1 : 0;
        }
        int kb = -1;
        if (cnt >= 1) {
            float up = (cnt <= 38) ? (3.25f + 1.25f * (float)cnt) * (3.25f + 1.25f * (float)cnt)
                                   : INFF;
            if (d2 < up) kb = cnt - 1;
        }

        const float* posj = pos + (long)rowj * 37 * 3;
        float tjx = posj[3] - cax, tjy = posj[4] - cay, tjz = posj[5] - caz;
        float r0 = M00 * tjx + M01 * tjy + M02 * tjz;
        float r1 = M10 * tjx + M11 * tjy + M12 * tjz;
        float r2 = M20 * tjx + M21 * tjy + M22 * tjz;
        float inv = rsqrtf(EPSF + r0 * r0 + r1 * r1 + r2 * r2);

        float fj  = aamask[rowj * 37 + 0] * aamask[rowj * 37 + 1] * aamask[rowj * 37 + 2];
        float f2d = fmask_i * fj;
        inv *= f2d;

        jA[j] = make_float4(r0 * inv, r1 * inv, r2 * inv, f2d);
        jB[j] = make_float4(pbm_i * pbmask[rowj],
                            __int_as_float(kb),
                            __int_as_float(aatype[rowj]),
                            0.0f);
    }
    __syncthreads();

    // ---- phase 2: gather-combine and stream stores ----
    const int og = tid & 15;    // o-group: outputs [og*4, og*4+4)
    const int jl = tid >> 4;    // j lane within 16-wide tile

    const float4* W4 = (const float4*)Wsm;   // W4[c*16 + og]
    const float4 b4  = ((const float4*)bvec)[og];
    const float4 w39 = W4[39 * 16 + og];
    const float4 w84 = W4[84 * 16 + og];
    const float4 w85 = W4[85 * 16 + og];
    const float4 w86 = W4[86 * 16 + og];
    const float4 wai = W4[(62 + aai) * 16 + og];
    const float4 w87 = W4[87 * 16 + og];
    const float base_x = wai.x + w87.x;
    const float base_y = wai.y + w87.y;
    const float base_z = wai.z + w87.z;
    const float base_w = wai.w + w87.w;

    float4* outp = (float4*)out + (long)bid * NRES * 16;   // 16 float4 per pair

#pragma unroll 4
    for (int jt = 0; jt < NRES / 16; jt++) {
        const int j = jt * 16 + jl;
        const float4 A = jA[j];
        const float4 B = jB[j];
        const int kb  = __float_as_int(B.y);
        const int aaj = __float_as_int(B.z);

        const float4 waj = W4[(40 + aaj) * 16 + og];
        float sx = base_x + waj.x;
        float sy = base_y + waj.y;
        float sz = base_z + waj.z;
        float sw = base_w + waj.w;

        if (kb >= 0) {   // uniform across the 16 lanes of this j
            const float4 wb = W4[kb * 16 + og];
            sx += wb.x; sy += wb.y; sz += wb.z; sw += wb.w;
        }

        sx = fmaf(B.x, w39.x, sx);
        sy = fmaf(B.x, w39.y, sy);
        sz = fmaf(B.x, w39.z, sz);
        sw = fmaf(B.x, w39.w, sw);

        sx = fmaf(A.x, w84.x, sx); sx = fmaf(A.y, w85.x, sx); sx = fmaf(A.z, w86.x, sx);
        sy = fmaf(A.x, w84.y, sy); sy = fmaf(A.y, w85.y, sy); sy = fmaf(A.z, w86.y, sy);
        sz = fmaf(A.x, w84.z, sz); sz = fmaf(A.y, w85.z, sz); sz = fmaf(A.z, w86.z, sz);
        sw = fmaf(A.x, w84.w, sw); sw = fmaf(A.y, w85.w, sw); sw = fmaf(A.z, w86.w, sw);

        float4 o4;
        o4.x = fmaf(A.w, sx, b4.x);
        o4.y = fmaf(A.w, sy, b4.y);
        o4.z = fmaf(A.w, sz, b4.z);
        o4.w = fmaf(A.w, sw, b4.w);
        outp[j * 16 + og] = o4;
    }
}

extern "C" void kernel_launch(void* const* d_in, const int* in_sizes, int n_in,
                              void* d_out, int out_size) {
    const float* pos    = (const float*)d_in[0];
    const float* tpb    = (const float*)d_in[1];
    const float* pbm    = (const float*)d_in[2];
    const float* aam    = (const float*)d_in[3];
    const int*   aaty   = (const int*)d_in[4];
    const float* W      = (const float*)d_in[5];
    const float* b      = (const float*)d_in[6];
    float* out = (float*)d_out;

    const int n_templ = in_sizes[4] / NRES;   // aatype elements = T*768
    tpe_kernel<<<n_templ * NRES, 256>>>(pos, tpb, pbm, aam, aaty, W, b, out);
}